// round 9
// baseline (speedup 1.0000x reference)
#include <cuda_runtime.h>
#include <cuda_fp16.h>

// Problem constants: N=100000, E=3200000, FEAT=128, HID=32, EMB=16
#define NMAX 100000
#define EMAX 3200000
#define SCAN_B 1024
#define NBLK ((NMAX + SCAN_B - 1) / SCAN_B)   // 98

// ---- scratch (device globals) ----
__device__ __half g_h1h[NMAX * 32];
__device__ float  g_hp1[NMAX * 32];
__device__ float  g_als1[NMAX], g_ald1[NMAX];
__device__ __half g_h2h[NMAX * 16];
__device__ float  g_als2[NMAX], g_ald2[NMAX];

__device__ int g_deg [NMAX];
__device__ int g_scan[NMAX];
__device__ int g_off [NMAX];
__device__ int g_bsum [NBLK];
__device__ int g_bsumx[NBLK];
__device__ int g_cnt;
__device__ int g_rank[EMAX];          // per-edge rank within its dst group
__device__ int2 g_epair[EMAX];        // CSR-ordered (src, w1-bits) pairs

__device__ __forceinline__ float leaky(float a) { return a > 0.0f ? a : 0.2f * a; }

// ===========================================================================
// Fused hist + node1. Blocks [0, histB): degree histogram capturing edge
// ranks. Blocks [histB, ...): node1 GEMM (fp32, one node per thread).
// ===========================================================================
__global__ __launch_bounds__(256) void hist_node1_kernel(
    const int* __restrict__ dst, int E,
    const float* __restrict__ x, const float* __restrict__ W1,
    const float* __restrict__ asrc, const float* __restrict__ adst, int N, int histB)
{
    if ((int)blockIdx.x < histB) {
        int t = blockIdx.x * 256 + threadIdx.x;
        int e = t * 4;
        if (e + 3 < E) {
            int4 d = *reinterpret_cast<const int4*>(dst + e);
            int4 r;
            r.x = atomicAdd(&g_deg[d.x], 1);
            r.y = atomicAdd(&g_deg[d.y], 1);
            r.z = atomicAdd(&g_deg[d.z], 1);
            r.w = atomicAdd(&g_deg[d.w], 1);
            *reinterpret_cast<int4*>(g_rank + e) = r;
        } else {
            for (; e < E; e++) g_rank[e] = atomicAdd(&g_deg[__ldg(dst + e)], 1);
        }
        return;
    }

    // ---- node1: h1 = x @ W1 (-> fp16); al_s1/al_d1 ----
    __shared__ float Ws[128 * 32];
    __shared__ float s_as[32], s_ad[32];
    for (int i = threadIdx.x; i < 128 * 32; i += 256) Ws[i] = W1[i];
    if (threadIdx.x < 32) { s_as[threadIdx.x] = asrc[threadIdx.x]; s_ad[threadIdx.x] = adst[threadIdx.x]; }
    __syncthreads();

    int n = (blockIdx.x - histB) * 256 + threadIdx.x;
    if (n >= N) return;

    float4 acc[8];
#pragma unroll
    for (int i = 0; i < 8; i++) acc[i] = make_float4(0.f, 0.f, 0.f, 0.f);

    const float4* xr = reinterpret_cast<const float4*>(x + (size_t)n * 128);
#pragma unroll 4
    for (int k4 = 0; k4 < 32; k4++) {
        float4 xv = __ldg(&xr[k4]);
        float xk[4] = {xv.x, xv.y, xv.z, xv.w};
#pragma unroll
        for (int kk = 0; kk < 4; kk++) {
            const float4* wr = reinterpret_cast<const float4*>(&Ws[(k4 * 4 + kk) * 32]);
            float xs = xk[kk];
#pragma unroll
            for (int c4 = 0; c4 < 8; c4++) {
                float4 w = wr[c4];
                acc[c4].x = fmaf(xs, w.x, acc[c4].x); acc[c4].y = fmaf(xs, w.y, acc[c4].y);
                acc[c4].z = fmaf(xs, w.z, acc[c4].z); acc[c4].w = fmaf(xs, w.w, acc[c4].w);
            }
        }
    }

    float als = 0.f, ald = 0.f;
#pragma unroll
    for (int c4 = 0; c4 < 8; c4++) {
        float4 a  = acc[c4];
        float4 s4 = reinterpret_cast<const float4*>(s_as)[c4];
        float4 d4 = reinterpret_cast<const float4*>(s_ad)[c4];
        als += a.x*s4.x + a.y*s4.y + a.z*s4.z + a.w*s4.w;
        ald += a.x*d4.x + a.y*d4.y + a.z*d4.z + a.w*d4.w;
    }
    g_als1[n] = als; g_ald1[n] = ald;

    __half2* hp = reinterpret_cast<__half2*>(&g_h1h[n * 32]);
#pragma unroll
    for (int c4 = 0; c4 < 8; c4++) {
        hp[c4 * 2]     = __floats2half2_rn(acc[c4].x, acc[c4].y);
        hp[c4 * 2 + 1] = __floats2half2_rn(acc[c4].z, acc[c4].w);
    }
}

// ===========================================================================
// scan1: per-block inclusive scan + block sums; last block also scans sums.
// ===========================================================================
__global__ __launch_bounds__(SCAN_B) void scan1_kernel(int N, int nb) {
    __shared__ int sh[SCAN_B];
    int gid = blockIdx.x * SCAN_B + threadIdx.x;
    int v = (gid < N) ? g_deg[gid] : 0;
    sh[threadIdx.x] = v;
    __syncthreads();
#pragma unroll
    for (int o = 1; o < SCAN_B; o <<= 1) {
        int t = (threadIdx.x >= o) ? sh[threadIdx.x - o] : 0;
        __syncthreads();
        sh[threadIdx.x] += t;
        __syncthreads();
    }
    if (gid < N) g_scan[gid] = sh[threadIdx.x];
    __shared__ int s_last;
    if (threadIdx.x == SCAN_B - 1) {
        g_bsum[blockIdx.x] = sh[SCAN_B - 1];
        __threadfence();
        s_last = (atomicAdd(&g_cnt, 1) == nb - 1);
    }
    __syncthreads();
    if (s_last) {
        __shared__ int sb[128];
        int t = threadIdx.x;
        if (t < 128) {
            int bv = (t < nb) ? g_bsum[t] : 0;
            sb[t] = bv;
            __syncthreads();
#pragma unroll
            for (int o = 1; o < 128; o <<= 1) {
                int u = (t >= o) ? sb[t - o] : 0;
                __syncthreads();
                sb[t] += u;
                __syncthreads();
            }
            if (t < nb) g_bsumx[t] = sb[t] - bv;
        }
    }
}

__global__ __launch_bounds__(256) void scan3_kernel(int N) {
    int gid = blockIdx.x * 256 + threadIdx.x;
    if (gid < N)
        g_off[gid] = g_scan[gid] - g_deg[gid] + g_bsumx[gid / SCAN_B];
}

// ===========================================================================
// permute: atomic-free; also computes the layer-1 edge weight and scatters
// the (src, w1) pair — an 8B scattered store costs the same sectors as 4B.
// ===========================================================================
__global__ __launch_bounds__(256) void permute_kernel(
    const int* __restrict__ src, const int* __restrict__ dst, int E)
{
    int t = blockIdx.x * 256 + threadIdx.x;
    int e = t * 4;
    if (e + 3 < E) {
        int4 d = *reinterpret_cast<const int4*>(dst + e);
        int4 r = *reinterpret_cast<const int4*>(g_rank + e);
        int4 s = *reinterpret_cast<const int4*>(src + e);
        // independent gathers (MLP=8) hide under the scatter latency
        float as0 = __ldg(&g_als1[s.x]), ad0 = __ldg(&g_ald1[d.x]);
        float as1 = __ldg(&g_als1[s.y]), ad1 = __ldg(&g_ald1[d.y]);
        float as2 = __ldg(&g_als1[s.z]), ad2 = __ldg(&g_ald1[d.z]);
        float as3 = __ldg(&g_als1[s.w]), ad3 = __ldg(&g_ald1[d.w]);
        int p0 = __ldg(&g_off[d.x]) + r.x;
        int p1 = __ldg(&g_off[d.y]) + r.y;
        int p2 = __ldg(&g_off[d.z]) + r.z;
        int p3 = __ldg(&g_off[d.w]) + r.w;
        float w0 = __expf(leaky(as0 + ad0));
        float w1 = __expf(leaky(as1 + ad1));
        float w2 = __expf(leaky(as2 + ad2));
        float w3 = __expf(leaky(as3 + ad3));
        g_epair[p0] = make_int2(s.x, __float_as_int(w0));
        g_epair[p1] = make_int2(s.y, __float_as_int(w1));
        g_epair[p2] = make_int2(s.z, __float_as_int(w2));
        g_epair[p3] = make_int2(s.w, __float_as_int(w3));
    } else {
        for (; e < E; e++) {
            int d = __ldg(dst + e);
            int sv = __ldg(src + e);
            float w = __expf(leaky(__ldg(&g_als1[sv]) + __ldg(&g_ald1[d])));
            g_epair[__ldg(&g_off[d]) + g_rank[e]] = make_int2(sv, __float_as_int(w));
        }
    }
}

// ===========================================================================
// agg1: layer-1 aggregate. TWO nodes per warp, 16 lanes each, pipelined.
// Consumes precomputed (src, w) pairs — no random als gather, no exp.
// ===========================================================================
__global__ __launch_bounds__(256) void agg1_kernel(const float* __restrict__ b1, int N)
{
    int wid = (blockIdx.x * 256 + threadIdx.x) >> 5;
    int lane = threadIdx.x & 31;
    int half = lane >> 4;
    int l16 = lane & 15;
    int n = wid * 2 + half;
    if (wid * 2 >= N) return;
    bool nvalid = (n < N);
    int nn = nvalid ? n : (N - 1);

    int start = g_off[nn];
    int deg = g_deg[nn];
    int end = start + deg;

    int nb = (deg + 15) >> 4;
    { int t = __shfl_xor_sync(0xffffffffu, nb, 16); nb = nb > t ? nb : t; }

    int s = 0; float w = 0.f;
    {
        int idx = start + l16;
        if (nvalid && idx < end) {
            int2 pr = __ldg(&g_epair[idx]);
            s = pr.x; w = __int_as_float(pr.y);
        }
    }

    float2 a0 = make_float2(0.f,0.f), a1 = make_float2(0.f,0.f);
    float2 a2 = make_float2(0.f,0.f), a3 = make_float2(0.f,0.f);
    float den = 0.f;
    const __half2* h1p = reinterpret_cast<const __half2*>(g_h1h);
    for (int b = 0; b < nb; b++) {
        int idx2 = start + (b + 1) * 16 + l16;
        int s2 = 0; float w2v = 0.f;
        if (nvalid && idx2 < end) {
            int2 pr = __ldg(&g_epair[idx2]);
            s2 = pr.x; w2v = __int_as_float(pr.y);
        }

        den += w;
#pragma unroll
        for (int j = 0; j < 16; j += 4) {
            int   s0 = __shfl_sync(0xffffffffu, s, j,     16);
            int   s1 = __shfl_sync(0xffffffffu, s, j + 1, 16);
            int   s2b= __shfl_sync(0xffffffffu, s, j + 2, 16);
            int   s3 = __shfl_sync(0xffffffffu, s, j + 3, 16);
            float w0 = __shfl_sync(0xffffffffu, w, j,     16);
            float w1 = __shfl_sync(0xffffffffu, w, j + 1, 16);
            float w2 = __shfl_sync(0xffffffffu, w, j + 2, 16);
            float w3 = __shfl_sync(0xffffffffu, w, j + 3, 16);
            float2 f0 = __half22float2(__ldg(&h1p[s0 * 16 + l16]));
            float2 f1 = __half22float2(__ldg(&h1p[s1 * 16 + l16]));
            float2 f2 = __half22float2(__ldg(&h1p[s2b* 16 + l16]));
            float2 f3 = __half22float2(__ldg(&h1p[s3 * 16 + l16]));
            a0.x = fmaf(w0, f0.x, a0.x); a0.y = fmaf(w0, f0.y, a0.y);
            a1.x = fmaf(w1, f1.x, a1.x); a1.y = fmaf(w1, f1.y, a1.y);
            a2.x = fmaf(w2, f2.x, a2.x); a2.y = fmaf(w2, f2.y, a2.y);
            a3.x = fmaf(w3, f3.x, a3.x); a3.y = fmaf(w3, f3.y, a3.y);
        }
        s = s2;
        w = w2v;
    }
    float2 acc = make_float2((a0.x + a1.x) + (a2.x + a3.x), (a0.y + a1.y) + (a2.y + a3.y));
#pragma unroll
    for (int o = 8; o; o >>= 1) den += __shfl_xor_sync(0xffffffffu, den, o, 16);

    float wself = __expf(leaky(__ldg(&g_als1[nn]) + __ldg(&g_ald1[nn])));
    den += wself;
    float2 hs = __half22float2(__ldg(&h1p[nn * 16 + l16]));
    acc.x = fmaf(wself, hs.x, acc.x);
    acc.y = fmaf(wself, hs.y, acc.y);

    float inv = 1.0f / (den + 1e-16f);
    if (nvalid) {
        float2 bv = __ldg(&reinterpret_cast<const float2*>(b1)[l16]);
        float2 r;
        r.x = fmaxf(fmaf(acc.x, inv, bv.x), 0.f);
        r.y = fmaxf(fmaf(acc.y, inv, bv.y), 0.f);
        reinterpret_cast<float2*>(&g_hp1[n * 32])[l16] = r;
    }
}

// ===========================================================================
// node2: h2 = h' @ W2 (-> fp16); al_s2/al_d2
// ===========================================================================
__global__ __launch_bounds__(256) void node2_kernel(
    const float* __restrict__ W2,
    const float* __restrict__ asrc, const float* __restrict__ adst, int N)
{
    __shared__ float Ws[32 * 16];
    __shared__ float s_as[16], s_ad[16];
    for (int i = threadIdx.x; i < 32 * 16; i += 256) Ws[i] = W2[i];
    if (threadIdx.x < 16) { s_as[threadIdx.x] = asrc[threadIdx.x]; s_ad[threadIdx.x] = adst[threadIdx.x]; }
    __syncthreads();

    int n = blockIdx.x * 256 + threadIdx.x;
    if (n >= N) return;

    float4 h2[4];
#pragma unroll
    for (int i = 0; i < 4; i++) h2[i] = make_float4(0.f, 0.f, 0.f, 0.f);

    const float4* hp = reinterpret_cast<const float4*>(&g_hp1[n * 32]);
#pragma unroll
    for (int c4 = 0; c4 < 8; c4++) {
        float4 xv = hp[c4];
        float xk[4] = {xv.x, xv.y, xv.z, xv.w};
#pragma unroll
        for (int kk = 0; kk < 4; kk++) {
            const float4* wr = reinterpret_cast<const float4*>(&Ws[(c4 * 4 + kk) * 16]);
            float xs = xk[kk];
#pragma unroll
            for (int o4 = 0; o4 < 4; o4++) {
                float4 w = wr[o4];
                h2[o4].x = fmaf(xs, w.x, h2[o4].x); h2[o4].y = fmaf(xs, w.y, h2[o4].y);
                h2[o4].z = fmaf(xs, w.z, h2[o4].z); h2[o4].w = fmaf(xs, w.w, h2[o4].w);
            }
        }
    }

    float als = 0.f, ald = 0.f;
#pragma unroll
    for (int o4 = 0; o4 < 4; o4++) {
        float4 a  = h2[o4];
        float4 s4 = reinterpret_cast<const float4*>(s_as)[o4];
        float4 d4 = reinterpret_cast<const float4*>(s_ad)[o4];
        als += a.x*s4.x + a.y*s4.y + a.z*s4.z + a.w*s4.w;
        ald += a.x*d4.x + a.y*d4.y + a.z*d4.z + a.w*d4.w;
    }
    g_als2[n] = als; g_ald2[n] = ald;

    __half2* out = reinterpret_cast<__half2*>(&g_h2h[n * 16]);
#pragma unroll
    for (int o4 = 0; o4 < 4; o4++) {
        out[o4 * 2]     = __floats2half2_rn(h2[o4].x, h2[o4].y);
        out[o4 * 2 + 1] = __floats2half2_rn(h2[o4].z, h2[o4].w);
    }
}

// ===========================================================================
// agg2: layer-2 aggregate + output. FOUR nodes per warp, 8 lanes, pipelined.
// src comes from g_epair[].x; weight recomputed (layer-2 alphas).
// ===========================================================================
__global__ __launch_bounds__(256) void agg2_kernel(
    const float* __restrict__ b2, float* __restrict__ out, int N)
{
    int wid = (blockIdx.x * 256 + threadIdx.x) >> 5;
    int lane = threadIdx.x & 31;
    int quad = lane >> 3;
    int l8 = lane & 7;
    int n = wid * 4 + quad;
    if (wid * 4 >= N) return;
    bool nvalid = (n < N);
    int nn = nvalid ? n : (N - 1);

    float ald = __ldg(&g_ald2[nn]);
    int start = g_off[nn];
    int deg = g_deg[nn];
    int end = start + deg;

    int nb = (deg + 7) >> 3;
    { int t = __shfl_xor_sync(0xffffffffu, nb, 8);  nb = nb > t ? nb : t; }
    { int t = __shfl_xor_sync(0xffffffffu, nb, 16); nb = nb > t ? nb : t; }

    int s = 0; float w;
    {
        int idx = start + l8;
        bool v = nvalid && idx < end;
        float al = 0.f;
        if (v) { s = __ldg(&g_epair[idx]).x; al = __ldg(&g_als2[s]); }
        w = v ? __expf(leaky(al + ald)) : 0.f;
    }

    float2 a0 = make_float2(0.f,0.f), a1 = make_float2(0.f,0.f);
    float2 a2 = make_float2(0.f,0.f), a3 = make_float2(0.f,0.f);
    float den = 0.f;
    const __half2* h2p = reinterpret_cast<const __half2*>(g_h2h);
    for (int b = 0; b < nb; b++) {
        int idx2 = start + (b + 1) * 8 + l8;
        bool v2 = nvalid && idx2 < end;
        int s2 = 0; float al2 = 0.f;
        if (v2) { s2 = __ldg(&g_epair[idx2]).x; al2 = __ldg(&g_als2[s2]); }

        den += w;
#pragma unroll
        for (int j = 0; j < 8; j += 4) {
            int   s0 = __shfl_sync(0xffffffffu, s, j,     8);
            int   s1 = __shfl_sync(0xffffffffu, s, j + 1, 8);
            int   s2b= __shfl_sync(0xffffffffu, s, j + 2, 8);
            int   s3 = __shfl_sync(0xffffffffu, s, j + 3, 8);
            float w0 = __shfl_sync(0xffffffffu, w, j,     8);
            float w1 = __shfl_sync(0xffffffffu, w, j + 1, 8);
            float w2 = __shfl_sync(0xffffffffu, w, j + 2, 8);
            float w3 = __shfl_sync(0xffffffffu, w, j + 3, 8);
            float2 f0 = __half22float2(__ldg(&h2p[s0 * 8 + l8]));
            float2 f1 = __half22float2(__ldg(&h2p[s1 * 8 + l8]));
            float2 f2 = __half22float2(__ldg(&h2p[s2b* 8 + l8]));
            float2 f3 = __half22float2(__ldg(&h2p[s3 * 8 + l8]));
            a0.x = fmaf(w0, f0.x, a0.x); a0.y = fmaf(w0, f0.y, a0.y);
            a1.x = fmaf(w1, f1.x, a1.x); a1.y = fmaf(w1, f1.y, a1.y);
            a2.x = fmaf(w2, f2.x, a2.x); a2.y = fmaf(w2, f2.y, a2.y);
            a3.x = fmaf(w3, f3.x, a3.x); a3.y = fmaf(w3, f3.y, a3.y);
        }
        s = s2;
        w = v2 ? __expf(leaky(al2 + ald)) : 0.f;
    }
    float2 acc = make_float2((a0.x + a1.x) + (a2.x + a3.x), (a0.y + a1.y) + (a2.y + a3.y));
#pragma unroll
    for (int o = 4; o; o >>= 1) den += __shfl_xor_sync(0xffffffffu, den, o, 8);

    float wself = __expf(leaky(__ldg(&g_als2[nn]) + ald));
    den += wself;
    float2 hs = __half22float2(__ldg(&h2p[nn * 8 + l8]));
    acc.x = fmaf(wself, hs.x, acc.x);
    acc.y = fmaf(wself, hs.y, acc.y);

    float inv = 1.0f / (den + 1e-16f);
    if (nvalid) {
        float2 bv = __ldg(&reinterpret_cast<const float2*>(b2)[l8]);
        float2 r;
        r.x = fmaf(acc.x, inv, bv.x);
        r.y = fmaf(acc.y, inv, bv.y);
        reinterpret_cast<float2*>(&out[n * 16])[l8] = r;
    }
}

// ===========================================================================
extern "C" void kernel_launch(void* const* d_in, const int* in_sizes, int n_in,
                              void* d_out, int out_size)
{
    const float* x   = (const float*)d_in[0];
    const int*   ei  = (const int*)  d_in[1];
    const float* W1  = (const float*)d_in[3];
    const float* as1 = (const float*)d_in[4];
    const float* ad1 = (const float*)d_in[5];
    const float* b1  = (const float*)d_in[6];
    const float* W2  = (const float*)d_in[7];
    const float* as2 = (const float*)d_in[8];
    const float* ad2 = (const float*)d_in[9];
    const float* b2  = (const float*)d_in[10];

    int N = in_sizes[0] / 128;
    int E = in_sizes[1] / 2;
    const int* src = ei;
    const int* dst = ei + E;

    void* p_deg = nullptr; cudaGetSymbolAddress(&p_deg, g_deg);
    void* p_cnt = nullptr; cudaGetSymbolAddress(&p_cnt, g_cnt);
    cudaMemsetAsync(p_deg, 0, (size_t)N * sizeof(int));
    cudaMemsetAsync(p_cnt, 0, sizeof(int));

    int nblkN = (N + 255) / 256;
    int nblkE4 = (E / 4 + 256) / 256;
    int nscan = (N + SCAN_B - 1) / SCAN_B;

    // fused hist (rank-capturing) + node1
    hist_node1_kernel<<<nblkE4 + nblkN, 256>>>(dst, E, x, W1, as1, ad1, N, nblkE4);

    scan1_kernel<<<nscan, SCAN_B>>>(N, nscan);
    scan3_kernel<<<nblkN, 256>>>(N);
    permute_kernel<<<nblkE4, 256>>>(src, dst, E);

    int nwarp1 = (((N + 1) / 2) * 32 + 255) / 256;
    agg1_kernel<<<nwarp1, 256>>>(b1, N);

    node2_kernel<<<nblkN, 256>>>(W2, as2, ad2, N);
    int nwarp2 = (((N + 3) / 4) * 32 + 255) / 256;
    agg2_kernel<<<nwarp2, 256>>>(b2, (float*)d_out, N);
}

// round 10
// speedup vs baseline: 1.0695x; 1.0695x over previous
#include <cuda_runtime.h>
#include <cuda_fp16.h>

// Problem constants: N=100000, E=3200000, FEAT=128, HID=32, EMB=16
#define NMAX 100000
#define EMAX 3200000
#define SCAN_B 1024
#define NBLK ((NMAX + SCAN_B - 1) / SCAN_B)   // 98

// ---- scratch (device globals) ----
__device__ __half g_h1h[NMAX * 32];
__device__ float  g_als1[NMAX], g_ald1[NMAX];
__device__ __half g_h2h[NMAX * 16];
__device__ float  g_als2[NMAX], g_ald2[NMAX];

__device__ int g_deg [NMAX];
__device__ int g_scan[NMAX];
__device__ int g_off [NMAX];
__device__ int g_bsum [NBLK];
__device__ int g_bsumx[NBLK];
__device__ int g_cnt;
__device__ int g_rank[EMAX];          // per-edge rank within its dst group
__device__ int g_esrc[EMAX];          // CSR-ordered srcs

__device__ __forceinline__ float leaky(float a) { return a > 0.0f ? a : 0.2f * a; }

// ===========================================================================
// Fused hist + node1. Blocks [0, histB): degree histogram capturing edge
// ranks. Blocks [histB, ...): node1 GEMM (fp32, one node per thread).
// ===========================================================================
__global__ __launch_bounds__(256) void hist_node1_kernel(
    const int* __restrict__ dst, int E,
    const float* __restrict__ x, const float* __restrict__ W1,
    const float* __restrict__ asrc, const float* __restrict__ adst, int N, int histB)
{
    if ((int)blockIdx.x < histB) {
        int t = blockIdx.x * 256 + threadIdx.x;
        int e = t * 4;
        if (e + 3 < E) {
            int4 d = *reinterpret_cast<const int4*>(dst + e);
            int4 r;
            r.x = atomicAdd(&g_deg[d.x], 1);
            r.y = atomicAdd(&g_deg[d.y], 1);
            r.z = atomicAdd(&g_deg[d.z], 1);
            r.w = atomicAdd(&g_deg[d.w], 1);
            *reinterpret_cast<int4*>(g_rank + e) = r;
        } else {
            for (; e < E; e++) g_rank[e] = atomicAdd(&g_deg[__ldg(dst + e)], 1);
        }
        return;
    }

    // ---- node1: h1 = x @ W1 (-> fp16); al_s1/al_d1 ----
    __shared__ float Ws[128 * 32];
    __shared__ float s_as[32], s_ad[32];
    for (int i = threadIdx.x; i < 128 * 32; i += 256) Ws[i] = W1[i];
    if (threadIdx.x < 32) { s_as[threadIdx.x] = asrc[threadIdx.x]; s_ad[threadIdx.x] = adst[threadIdx.x]; }
    __syncthreads();

    int n = (blockIdx.x - histB) * 256 + threadIdx.x;
    if (n >= N) return;

    float4 acc[8];
#pragma unroll
    for (int i = 0; i < 8; i++) acc[i] = make_float4(0.f, 0.f, 0.f, 0.f);

    const float4* xr = reinterpret_cast<const float4*>(x + (size_t)n * 128);
#pragma unroll 4
    for (int k4 = 0; k4 < 32; k4++) {
        float4 xv = __ldg(&xr[k4]);
        float xk[4] = {xv.x, xv.y, xv.z, xv.w};
#pragma unroll
        for (int kk = 0; kk < 4; kk++) {
            const float4* wr = reinterpret_cast<const float4*>(&Ws[(k4 * 4 + kk) * 32]);
            float xs = xk[kk];
#pragma unroll
            for (int c4 = 0; c4 < 8; c4++) {
                float4 w = wr[c4];
                acc[c4].x = fmaf(xs, w.x, acc[c4].x); acc[c4].y = fmaf(xs, w.y, acc[c4].y);
                acc[c4].z = fmaf(xs, w.z, acc[c4].z); acc[c4].w = fmaf(xs, w.w, acc[c4].w);
            }
        }
    }

    float als = 0.f, ald = 0.f;
#pragma unroll
    for (int c4 = 0; c4 < 8; c4++) {
        float4 a  = acc[c4];
        float4 s4 = reinterpret_cast<const float4*>(s_as)[c4];
        float4 d4 = reinterpret_cast<const float4*>(s_ad)[c4];
        als += a.x*s4.x + a.y*s4.y + a.z*s4.z + a.w*s4.w;
        ald += a.x*d4.x + a.y*d4.y + a.z*d4.z + a.w*d4.w;
    }
    g_als1[n] = als; g_ald1[n] = ald;

    __half2* hp = reinterpret_cast<__half2*>(&g_h1h[n * 32]);
#pragma unroll
    for (int c4 = 0; c4 < 8; c4++) {
        hp[c4 * 2]     = __floats2half2_rn(acc[c4].x, acc[c4].y);
        hp[c4 * 2 + 1] = __floats2half2_rn(acc[c4].z, acc[c4].w);
    }
}

// ===========================================================================
// scan1: per-block inclusive scan + block sums; last block also scans sums.
// ===========================================================================
__global__ __launch_bounds__(SCAN_B) void scan1_kernel(int N, int nb) {
    __shared__ int sh[SCAN_B];
    int gid = blockIdx.x * SCAN_B + threadIdx.x;
    int v = (gid < N) ? g_deg[gid] : 0;
    sh[threadIdx.x] = v;
    __syncthreads();
#pragma unroll
    for (int o = 1; o < SCAN_B; o <<= 1) {
        int t = (threadIdx.x >= o) ? sh[threadIdx.x - o] : 0;
        __syncthreads();
        sh[threadIdx.x] += t;
        __syncthreads();
    }
    if (gid < N) g_scan[gid] = sh[threadIdx.x];
    __shared__ int s_last;
    if (threadIdx.x == SCAN_B - 1) {
        g_bsum[blockIdx.x] = sh[SCAN_B - 1];
        __threadfence();
        s_last = (atomicAdd(&g_cnt, 1) == nb - 1);
    }
    __syncthreads();
    if (s_last) {
        __shared__ int sb[128];
        int t = threadIdx.x;
        if (t < 128) {
            int bv = (t < nb) ? g_bsum[t] : 0;
            sb[t] = bv;
            __syncthreads();
#pragma unroll
            for (int o = 1; o < 128; o <<= 1) {
                int u = (t >= o) ? sb[t - o] : 0;
                __syncthreads();
                sb[t] += u;
                __syncthreads();
            }
            if (t < nb) g_bsumx[t] = sb[t] - bv;
        }
    }
}

__global__ __launch_bounds__(256) void scan3_kernel(int N) {
    int gid = blockIdx.x * 256 + threadIdx.x;
    if (gid < N)
        g_off[gid] = g_scan[gid] - g_deg[gid] + g_bsumx[gid / SCAN_B];
}

// ===========================================================================
// permute: atomic-free. p = off[dst[e]] + rank[e]; esrc[p] = src[e]. (R8)
// ===========================================================================
__global__ __launch_bounds__(256) void permute_kernel(
    const int* __restrict__ src, const int* __restrict__ dst, int E)
{
    int t = blockIdx.x * 256 + threadIdx.x;
    int e = t * 4;
    if (e + 3 < E) {
        int4 d = *reinterpret_cast<const int4*>(dst + e);
        int4 r = *reinterpret_cast<const int4*>(g_rank + e);
        int4 s = *reinterpret_cast<const int4*>(src + e);
        int p0 = __ldg(&g_off[d.x]) + r.x;
        int p1 = __ldg(&g_off[d.y]) + r.y;
        int p2 = __ldg(&g_off[d.z]) + r.z;
        int p3 = __ldg(&g_off[d.w]) + r.w;
        g_esrc[p0] = s.x;
        g_esrc[p1] = s.y;
        g_esrc[p2] = s.z;
        g_esrc[p3] = s.w;
    } else {
        for (; e < E; e++) {
            int d = __ldg(dst + e);
            g_esrc[__ldg(&g_off[d]) + g_rank[e]] = __ldg(src + e);
        }
    }
}

// ===========================================================================
// agg1_node2 (fused): layer-1 aggregate (2 nodes/warp, 16 lanes each,
// pipelined), THEN in-block layer-2 GEMM via a shared 16-node tile.
// No early returns before __syncthreads.
// ===========================================================================
__global__ __launch_bounds__(256) void agg1_node2_kernel(
    const float* __restrict__ b1, const float* __restrict__ W2,
    const float* __restrict__ as2, const float* __restrict__ ad2, int N)
{
    __shared__ float s_hp1[16 * 34];   // 16 nodes x 32ch, stride 34 (conflict pad)
    __shared__ float W2s[32 * 16];
    __shared__ float s_as2[16], s_ad2[16];
    for (int i = threadIdx.x; i < 32 * 16; i += 256) W2s[i] = W2[i];
    if (threadIdx.x < 16) { s_as2[threadIdx.x] = as2[threadIdx.x]; s_ad2[threadIdx.x] = ad2[threadIdx.x]; }

    int wid = blockIdx.x * 8 + (threadIdx.x >> 5);
    int lane = threadIdx.x & 31;
    int half = lane >> 4;
    int l16 = lane & 15;
    int n = wid * 2 + half;
    bool nvalid = (n < N);
    int nn = nvalid ? n : (N - 1);

    float ald = __ldg(&g_ald1[nn]);
    int start = g_off[nn];
    int deg = g_deg[nn];
    int end = start + deg;

    int nb = (deg + 15) >> 4;
    { int t = __shfl_xor_sync(0xffffffffu, nb, 16); nb = nb > t ? nb : t; }

    int s = 0; float w;
    {
        int idx = start + l16;
        bool v = nvalid && idx < end;
        float al = 0.f;
        if (v) { s = __ldg(&g_esrc[idx]); al = __ldg(&g_als1[s]); }
        w = v ? __expf(leaky(al + ald)) : 0.f;
    }

    float2 a0 = make_float2(0.f,0.f), a1 = make_float2(0.f,0.f);
    float2 a2 = make_float2(0.f,0.f), a3 = make_float2(0.f,0.f);
    float den = 0.f;
    const __half2* h1p = reinterpret_cast<const __half2*>(g_h1h);
    for (int b = 0; b < nb; b++) {
        int idx2 = start + (b + 1) * 16 + l16;
        bool v2 = nvalid && idx2 < end;
        int s2 = 0; float al2 = 0.f;
        if (v2) { s2 = __ldg(&g_esrc[idx2]); al2 = __ldg(&g_als1[s2]); }

        den += w;
#pragma unroll
        for (int j = 0; j < 16; j += 4) {
            int   s0 = __shfl_sync(0xffffffffu, s, j,     16);
            int   s1 = __shfl_sync(0xffffffffu, s, j + 1, 16);
            int   s2b= __shfl_sync(0xffffffffu, s, j + 2, 16);
            int   s3 = __shfl_sync(0xffffffffu, s, j + 3, 16);
            float w0 = __shfl_sync(0xffffffffu, w, j,     16);
            float w1 = __shfl_sync(0xffffffffu, w, j + 1, 16);
            float w2 = __shfl_sync(0xffffffffu, w, j + 2, 16);
            float w3 = __shfl_sync(0xffffffffu, w, j + 3, 16);
            float2 f0 = __half22float2(__ldg(&h1p[s0 * 16 + l16]));
            float2 f1 = __half22float2(__ldg(&h1p[s1 * 16 + l16]));
            float2 f2 = __half22float2(__ldg(&h1p[s2b* 16 + l16]));
            float2 f3 = __half22float2(__ldg(&h1p[s3 * 16 + l16]));
            a0.x = fmaf(w0, f0.x, a0.x); a0.y = fmaf(w0, f0.y, a0.y);
            a1.x = fmaf(w1, f1.x, a1.x); a1.y = fmaf(w1, f1.y, a1.y);
            a2.x = fmaf(w2, f2.x, a2.x); a2.y = fmaf(w2, f2.y, a2.y);
            a3.x = fmaf(w3, f3.x, a3.x); a3.y = fmaf(w3, f3.y, a3.y);
        }
        s = s2;
        w = v2 ? __expf(leaky(al2 + ald)) : 0.f;
    }
    float2 acc = make_float2((a0.x + a1.x) + (a2.x + a3.x), (a0.y + a1.y) + (a2.y + a3.y));
#pragma unroll
    for (int o = 8; o; o >>= 1) den += __shfl_xor_sync(0xffffffffu, den, o, 16);

    float wself = __expf(leaky(__ldg(&g_als1[nn]) + ald));
    den += wself;
    float2 hs = __half22float2(__ldg(&h1p[nn * 16 + l16]));
    acc.x = fmaf(wself, hs.x, acc.x);
    acc.y = fmaf(wself, hs.y, acc.y);

    float inv = 1.0f / (den + 1e-16f);
    {
        float2 bv = __ldg(&reinterpret_cast<const float2*>(b1)[l16]);
        int nloc = threadIdx.x >> 4;   // 0..15, == local node index
        float* row = &s_hp1[nloc * 34];
        row[2 * l16]     = fmaxf(fmaf(acc.x, inv, bv.x), 0.f);
        row[2 * l16 + 1] = fmaxf(fmaf(acc.y, inv, bv.y), 0.f);
    }
    __syncthreads();

    // ---- phase 2: h2 = hp1 @ W2; als2/ald2. thread t: node t>>4, chan t&15.
    int nloc = threadIdx.x >> 4;
    int o = threadIdx.x & 15;
    int n2 = blockIdx.x * 16 + nloc;
    if (n2 < N) {
        const float* row = &s_hp1[nloc * 34];
        float h2 = 0.f;
#pragma unroll
        for (int c = 0; c < 32; c++)
            h2 = fmaf(row[c], W2s[c * 16 + o], h2);
        g_h2h[n2 * 16 + o] = __float2half_rn(h2);
        float pa = h2 * s_as2[o];
        float pd = h2 * s_ad2[o];
#pragma unroll
        for (int off = 8; off; off >>= 1) {
            pa += __shfl_xor_sync(0xffffffffu, pa, off, 16);
            pd += __shfl_xor_sync(0xffffffffu, pd, off, 16);
        }
        if (o == 0) { g_als2[n2] = pa; g_ald2[n2] = pd; }
    }
}

// ===========================================================================
// agg2: layer-2 aggregate + output. FOUR nodes per warp, 8 lanes, pipelined.
// ===========================================================================
__global__ __launch_bounds__(256) void agg2_kernel(
    const float* __restrict__ b2, float* __restrict__ out, int N)
{
    int wid = (blockIdx.x * 256 + threadIdx.x) >> 5;
    int lane = threadIdx.x & 31;
    int quad = lane >> 3;
    int l8 = lane & 7;
    int n = wid * 4 + quad;
    if (wid * 4 >= N) return;
    bool nvalid = (n < N);
    int nn = nvalid ? n : (N - 1);

    float ald = __ldg(&g_ald2[nn]);
    int start = g_off[nn];
    int deg = g_deg[nn];
    int end = start + deg;

    int nb = (deg + 7) >> 3;
    { int t = __shfl_xor_sync(0xffffffffu, nb, 8);  nb = nb > t ? nb : t; }
    { int t = __shfl_xor_sync(0xffffffffu, nb, 16); nb = nb > t ? nb : t; }

    int s = 0; float w;
    {
        int idx = start + l8;
        bool v = nvalid && idx < end;
        float al = 0.f;
        if (v) { s = __ldg(&g_esrc[idx]); al = __ldg(&g_als2[s]); }
        w = v ? __expf(leaky(al + ald)) : 0.f;
    }

    float2 a0 = make_float2(0.f,0.f), a1 = make_float2(0.f,0.f);
    float2 a2 = make_float2(0.f,0.f), a3 = make_float2(0.f,0.f);
    float den = 0.f;
    const __half2* h2p = reinterpret_cast<const __half2*>(g_h2h);
    for (int b = 0; b < nb; b++) {
        int idx2 = start + (b + 1) * 8 + l8;
        bool v2 = nvalid && idx2 < end;
        int s2 = 0; float al2 = 0.f;
        if (v2) { s2 = __ldg(&g_esrc[idx2]); al2 = __ldg(&g_als2[s2]); }

        den += w;
#pragma unroll
        for (int j = 0; j < 8; j += 4) {
            int   s0 = __shfl_sync(0xffffffffu, s, j,     8);
            int   s1 = __shfl_sync(0xffffffffu, s, j + 1, 8);
            int   s2b= __shfl_sync(0xffffffffu, s, j + 2, 8);
            int   s3 = __shfl_sync(0xffffffffu, s, j + 3, 8);
            float w0 = __shfl_sync(0xffffffffu, w, j,     8);
            float w1 = __shfl_sync(0xffffffffu, w, j + 1, 8);
            float w2 = __shfl_sync(0xffffffffu, w, j + 2, 8);
            float w3 = __shfl_sync(0xffffffffu, w, j + 3, 8);
            float2 f0 = __half22float2(__ldg(&h2p[s0 * 8 + l8]));
            float2 f1 = __half22float2(__ldg(&h2p[s1 * 8 + l8]));
            float2 f2 = __half22float2(__ldg(&h2p[s2b* 8 + l8]));
            float2 f3 = __half22float2(__ldg(&h2p[s3 * 8 + l8]));
            a0.x = fmaf(w0, f0.x, a0.x); a0.y = fmaf(w0, f0.y, a0.y);
            a1.x = fmaf(w1, f1.x, a1.x); a1.y = fmaf(w1, f1.y, a1.y);
            a2.x = fmaf(w2, f2.x, a2.x); a2.y = fmaf(w2, f2.y, a2.y);
            a3.x = fmaf(w3, f3.x, a3.x); a3.y = fmaf(w3, f3.y, a3.y);
        }
        s = s2;
        w = v2 ? __expf(leaky(al2 + ald)) : 0.f;
    }
    float2 acc = make_float2((a0.x + a1.x) + (a2.x + a3.x), (a0.y + a1.y) + (a2.y + a3.y));
#pragma unroll
    for (int o = 4; o; o >>= 1) den += __shfl_xor_sync(0xffffffffu, den, o, 8);

    float wself = __expf(leaky(__ldg(&g_als2[nn]) + ald));
    den += wself;
    float2 hs = __half22float2(__ldg(&h2p[nn * 8 + l8]));
    acc.x = fmaf(wself, hs.x, acc.x);
    acc.y = fmaf(wself, hs.y, acc.y);

    float inv = 1.0f / (den + 1e-16f);
    if (nvalid) {
        float2 bv = __ldg(&reinterpret_cast<const float2*>(b2)[l8]);
        float2 r;
        r.x = fmaf(acc.x, inv, bv.x);
        r.y = fmaf(acc.y, inv, bv.y);
        reinterpret_cast<float2*>(&out[n * 16])[l8] = r;
    }
}

// ===========================================================================
extern "C" void kernel_launch(void* const* d_in, const int* in_sizes, int n_in,
                              void* d_out, int out_size)
{
    const float* x   = (const float*)d_in[0];
    const int*   ei  = (const int*)  d_in[1];
    const float* W1  = (const float*)d_in[3];
    const float* as1 = (const float*)d_in[4];
    const float* ad1 = (const float*)d_in[5];
    const float* b1  = (const float*)d_in[6];
    const float* W2  = (const float*)d_in[7];
    const float* as2 = (const float*)d_in[8];
    const float* ad2 = (const float*)d_in[9];
    const float* b2  = (const float*)d_in[10];

    int N = in_sizes[0] / 128;
    int E = in_sizes[1] / 2;
    const int* src = ei;
    const int* dst = ei + E;

    void* p_deg = nullptr; cudaGetSymbolAddress(&p_deg, g_deg);
    void* p_cnt = nullptr; cudaGetSymbolAddress(&p_cnt, g_cnt);
    cudaMemsetAsync(p_deg, 0, (size_t)N * sizeof(int));
    cudaMemsetAsync(p_cnt, 0, sizeof(int));

    int nblkN = (N + 255) / 256;
    int nblkE4 = (E / 4 + 256) / 256;
    int nscan = (N + SCAN_B - 1) / SCAN_B;

    // fused hist (rank-capturing) + node1
    hist_node1_kernel<<<nblkE4 + nblkN, 256>>>(dst, E, x, W1, as1, ad1, N, nblkE4);

    scan1_kernel<<<nscan, SCAN_B>>>(N, nscan);
    scan3_kernel<<<nblkN, 256>>>(N);
    permute_kernel<<<nblkE4, 256>>>(src, dst, E);

    // fused agg1 + node2 (16 nodes per block)
    agg1_node2_kernel<<<(N + 15) / 16, 256>>>(b1, W2, as2, ad2, N);

    int nwarp2 = (((N + 3) / 4) * 32 + 255) / 256;
    agg2_kernel<<<nwarp2, 256>>>(b2, (float*)d_out, N);
}